// round 1
// baseline (speedup 1.0000x reference)
#include <cuda_runtime.h>
#include <math.h>

#define NB 16
#define NS 2048
#define NH 1024
#define NCOEF 7          // A0, A1, B1, A2, B2, A3, B3
#define NCHUNK 8
#define SCHUNK (NS / NCHUNK)   // 256
#define LN_EPS 1e-12f

// twiddles: per s, {cos1,sin1,cos2,sin2,cos3,sin3}
__device__ float g_tw[NS][6];
// deterministic partial reductions, then final coefficients
__device__ float g_partial[NCHUNK][NB][NCOEF][NH];
__device__ float g_coeff[NB][NCOEF][NH];

// ---------------------------------------------------------------------------
// Kernel 0: twiddle table (exact-ish via double sincos)
// ---------------------------------------------------------------------------
__global__ void twiddle_kernel() {
    int s = blockIdx.x * blockDim.x + threadIdx.x;
    if (s >= NS) return;
#pragma unroll
    for (int k = 1; k <= 3; k++) {
        double ang = 2.0 * M_PI * (double)(k * s) / (double)NS;
        g_tw[s][2 * (k - 1)]     = (float)cos(ang);
        g_tw[s][2 * (k - 1) + 1] = (float)sin(ang);
    }
}

// ---------------------------------------------------------------------------
// Kernel 1: partial DFT coefficient sums.
// grid = (NB, NH/256, NCHUNK), block = 256 (one thread per h, coalesced loads)
// ---------------------------------------------------------------------------
__global__ void __launch_bounds__(256) coeff_partial_kernel(const float* __restrict__ x) {
    const int b     = blockIdx.x;
    const int h     = blockIdx.y * 256 + threadIdx.x;
    const int chunk = blockIdx.z;
    const int s0    = chunk * SCHUNK;

    __shared__ float tw[SCHUNK][6];
    for (int i = threadIdx.x; i < SCHUNK * 6; i += 256)
        (&tw[0][0])[i] = (&g_tw[0][0])[s0 * 6 + i];
    __syncthreads();

    float a0 = 0.f, a1 = 0.f, b1 = 0.f, a2 = 0.f, b2 = 0.f, a3 = 0.f, b3 = 0.f;
    const float* __restrict__ xp = x + ((size_t)b * NS + s0) * NH + h;

#pragma unroll 8
    for (int j = 0; j < SCHUNK; j++) {
        float v = xp[(size_t)j * NH];
        a0 += v;
        a1 += v * tw[j][0];  b1 += v * tw[j][1];
        a2 += v * tw[j][2];  b2 += v * tw[j][3];
        a3 += v * tw[j][4];  b3 += v * tw[j][5];
    }

    g_partial[chunk][b][0][h] = a0;
    g_partial[chunk][b][1][h] = a1;
    g_partial[chunk][b][2][h] = b1;
    g_partial[chunk][b][3][h] = a2;
    g_partial[chunk][b][4][h] = b2;
    g_partial[chunk][b][5][h] = a3;
    g_partial[chunk][b][6][h] = b3;
}

// ---------------------------------------------------------------------------
// Kernel 2: reduce the NCHUNK partials (deterministic order)
// ---------------------------------------------------------------------------
__global__ void coeff_reduce_kernel() {
    int i = blockIdx.x * blockDim.x + threadIdx.x;
    const int N = NB * NCOEF * NH;
    if (i >= N) return;
    const float* p = &g_partial[0][0][0][0];
    float s = 0.f;
#pragma unroll
    for (int c = 0; c < NCHUNK; c++) s += p[(size_t)c * N + i];
    (&g_coeff[0][0][0])[i] = s;
}

// ---------------------------------------------------------------------------
// Kernel 3: fused recombine + LayerNorm. One block per (b, s) row.
// 256 threads, each handles one float4 (4 h values).
// ---------------------------------------------------------------------------
__global__ void __launch_bounds__(256) fuse_ln_kernel(
    const float* __restrict__ x,
    const float* __restrict__ sqrt_beta,
    const float* __restrict__ gamma,
    const float* __restrict__ beta,
    float* __restrict__ out)
{
    const int row = blockIdx.x;          // b*NS + s
    const int b   = row >> 11;           // / 2048
    const int s   = row & (NS - 1);
    const int tid = threadIdx.x;

    const float c1 = g_tw[s][0], s1 = g_tw[s][1];
    const float c2 = g_tw[s][2], s2 = g_tw[s][3];
    const float c3 = g_tw[s][4], s3 = g_tw[s][5];
    const float inv_s = 1.0f / (float)NS;

    const float4 xv  = ((const float4*)(x + (size_t)row * NH))[tid];
    const float4 A0v = ((const float4*)g_coeff[b][0])[tid];
    const float4 A1v = ((const float4*)g_coeff[b][1])[tid];
    const float4 B1v = ((const float4*)g_coeff[b][2])[tid];
    const float4 A2v = ((const float4*)g_coeff[b][3])[tid];
    const float4 B2v = ((const float4*)g_coeff[b][4])[tid];
    const float4 A3v = ((const float4*)g_coeff[b][5])[tid];
    const float4 B3v = ((const float4*)g_coeff[b][6])[tid];
    const float4 sb  = ((const float4*)sqrt_beta)[tid];

    float4 val;
#define DO_LANE(L)                                                            \
    {                                                                         \
        float low = (A0v.L + 2.0f * (A1v.L * c1 + B1v.L * s1 +               \
                                     A2v.L * c2 + B2v.L * s2 +               \
                                     A3v.L * c3 + B3v.L * s3)) * inv_s;      \
        float sb2 = sb.L * sb.L;                                             \
        val.L = low + sb2 * (xv.L - low) + xv.L;                             \
    }
    DO_LANE(x) DO_LANE(y) DO_LANE(z) DO_LANE(w)
#undef DO_LANE

    float lsum = val.x + val.y + val.z + val.w;
    float lsq  = val.x * val.x + val.y * val.y + val.z * val.z + val.w * val.w;

    // block reduction: warp shuffle, then across 8 warps via smem
    const int lane = tid & 31, w = tid >> 5;
#pragma unroll
    for (int o = 16; o > 0; o >>= 1) {
        lsum += __shfl_down_sync(0xffffffffu, lsum, o);
        lsq  += __shfl_down_sync(0xffffffffu, lsq,  o);
    }
    __shared__ float2 sred[8];
    if (lane == 0) sred[w] = make_float2(lsum, lsq);
    __syncthreads();
    if (w == 0) {
        float a  = (lane < 8) ? sred[lane].x : 0.f;
        float b2 = (lane < 8) ? sred[lane].y : 0.f;
#pragma unroll
        for (int o = 4; o > 0; o >>= 1) {
            a  += __shfl_down_sync(0xffffffffu, a,  o);
            b2 += __shfl_down_sync(0xffffffffu, b2, o);
        }
        if (lane == 0) sred[0] = make_float2(a, b2);
    }
    __syncthreads();

    const float mean = sred[0].x * (1.0f / (float)NH);
    const float var  = sred[0].y * (1.0f / (float)NH) - mean * mean;
    const float rstd = rsqrtf(var + LN_EPS);

    const float4 gv  = ((const float4*)gamma)[tid];
    const float4 bev = ((const float4*)beta)[tid];

    float4 o4;
    o4.x = (val.x - mean) * rstd * gv.x + bev.x;
    o4.y = (val.y - mean) * rstd * gv.y + bev.y;
    o4.z = (val.z - mean) * rstd * gv.z + bev.z;
    o4.w = (val.w - mean) * rstd * gv.w + bev.w;
    ((float4*)(out + (size_t)row * NH))[tid] = o4;
}

// ---------------------------------------------------------------------------
// launch
// ---------------------------------------------------------------------------
extern "C" void kernel_launch(void* const* d_in, const int* in_sizes, int n_in,
                              void* d_out, int out_size) {
    const float* x         = (const float*)d_in[0];
    const float* sqrt_beta = (const float*)d_in[1];
    const float* ln_gamma  = (const float*)d_in[2];
    const float* ln_beta   = (const float*)d_in[3];
    float* out = (float*)d_out;

    twiddle_kernel<<<(NS + 255) / 256, 256>>>();

    dim3 g1(NB, NH / 256, NCHUNK);
    coeff_partial_kernel<<<g1, 256>>>(x);

    const int nred = NB * NCOEF * NH;
    coeff_reduce_kernel<<<(nred + 255) / 256, 256>>>();

    fuse_ln_kernel<<<NB * NS, 256>>>(x, sqrt_beta, ln_gamma, ln_beta, out);
}

// round 2
// speedup vs baseline: 1.0557x; 1.0557x over previous
#include <cuda_runtime.h>
#include <math.h>

#define NB 16
#define NS 2048
#define NH 1024
#define NH4 (NH / 4)
#define NCOEF 7          // C0, C1, S1, C2, S2, C3, S3
#define NCHUNK 32
#define SCHUNK (NS / NCHUNK)   // 64
#define ROWS 8                 // rows per block in fuse_ln
#define LN_EPS 1e-12f

// twiddles: per s, {cos1,sin1,cos2,sin2,cos3,sin3, pad, pad} (padded to 8 for float4 loads)
__device__ float g_tw[NS][8];
// deterministic partial reductions, then final (pre-scaled) coefficients
__device__ float g_partial[NCHUNK][NB][NCOEF][NH];
__device__ float g_coeff[NB][NCOEF][NH];

__device__ __forceinline__ float4 f4zero() { return make_float4(0.f, 0.f, 0.f, 0.f); }

// ---------------------------------------------------------------------------
// Kernel 0: twiddle table (double sincos for accuracy)
// ---------------------------------------------------------------------------
__global__ void twiddle_kernel() {
    int s = blockIdx.x * blockDim.x + threadIdx.x;
    if (s >= NS) return;
#pragma unroll
    for (int k = 1; k <= 3; k++) {
        double ang = 2.0 * M_PI * (double)(k * s) / (double)NS;
        g_tw[s][2 * (k - 1)]     = (float)cos(ang);
        g_tw[s][2 * (k - 1) + 1] = (float)sin(ang);
    }
    g_tw[s][6] = 0.f;
    g_tw[s][7] = 0.f;
}

// ---------------------------------------------------------------------------
// Kernel 1: partial DFT coefficient sums, float4-vectorized.
// grid = (NB, NCHUNK), block = 256 (one thread per 4 h-values)
// ---------------------------------------------------------------------------
__global__ void __launch_bounds__(256) coeff_partial_kernel(const float* __restrict__ x) {
    const int b     = blockIdx.x;
    const int chunk = blockIdx.y;
    const int s0    = chunk * SCHUNK;
    const int tid   = threadIdx.x;

    __shared__ float tw[SCHUNK][8];
    for (int i = tid; i < SCHUNK * 8; i += 256)
        (&tw[0][0])[i] = (&g_tw[0][0])[s0 * 8 + i];
    __syncthreads();

    float4 a0 = f4zero(), a1 = f4zero(), b1 = f4zero(),
           a2 = f4zero(), b2 = f4zero(), a3 = f4zero(), b3 = f4zero();

    const float4* __restrict__ xp =
        (const float4*)(x + ((size_t)b * NS + s0) * NH) + tid;

#pragma unroll 8
    for (int j = 0; j < SCHUNK; j++) {
        float4 v = xp[(size_t)j * NH4];
        float c1 = tw[j][0], s1 = tw[j][1];
        float c2 = tw[j][2], s2 = tw[j][3];
        float c3 = tw[j][4], s3 = tw[j][5];
        a0.x += v.x; a0.y += v.y; a0.z += v.z; a0.w += v.w;
        a1.x += v.x * c1; a1.y += v.y * c1; a1.z += v.z * c1; a1.w += v.w * c1;
        b1.x += v.x * s1; b1.y += v.y * s1; b1.z += v.z * s1; b1.w += v.w * s1;
        a2.x += v.x * c2; a2.y += v.y * c2; a2.z += v.z * c2; a2.w += v.w * c2;
        b2.x += v.x * s2; b2.y += v.y * s2; b2.z += v.z * s2; b2.w += v.w * s2;
        a3.x += v.x * c3; a3.y += v.y * c3; a3.z += v.z * c3; a3.w += v.w * c3;
        b3.x += v.x * s3; b3.y += v.y * s3; b3.z += v.z * s3; b3.w += v.w * s3;
    }

    ((float4*)g_partial[chunk][b][0])[tid] = a0;
    ((float4*)g_partial[chunk][b][1])[tid] = a1;
    ((float4*)g_partial[chunk][b][2])[tid] = b1;
    ((float4*)g_partial[chunk][b][3])[tid] = a2;
    ((float4*)g_partial[chunk][b][4])[tid] = b2;
    ((float4*)g_partial[chunk][b][5])[tid] = a3;
    ((float4*)g_partial[chunk][b][6])[tid] = b3;
}

// ---------------------------------------------------------------------------
// Kernel 2: reduce NCHUNK partials (deterministic) and pre-scale:
//   C0 = A0 * (1-beta^2)/S ;  Ck = 2*Ak*(1-beta^2)/S ;  Sk = 2*Bk*(1-beta^2)/S
// so fuse_ln computes val = C0 + sum(Ck*ck + Sk*sk) + (1+beta^2)*x
// ---------------------------------------------------------------------------
__global__ void coeff_reduce_kernel(const float* __restrict__ sqrt_beta) {
    const int i = blockIdx.x * blockDim.x + threadIdx.x;   // float4 index
    const int N4 = NB * NCOEF * NH4;
    if (i >= N4) return;

    const int h4 = i % NH4;
    const int k  = (i / NH4) % NCOEF;

    const float4* p = (const float4*)&g_partial[0][0][0][0];
    float4 s = f4zero();
#pragma unroll
    for (int c = 0; c < NCHUNK; c++) {
        float4 v = p[(size_t)c * N4 + i];
        s.x += v.x; s.y += v.y; s.z += v.z; s.w += v.w;
    }

    const float4 sb = ((const float4*)sqrt_beta)[h4];
    const float base = (k == 0 ? 1.0f : 2.0f) / (float)NS;
    s.x *= (1.0f - sb.x * sb.x) * base;
    s.y *= (1.0f - sb.y * sb.y) * base;
    s.z *= (1.0f - sb.z * sb.z) * base;
    s.w *= (1.0f - sb.w * sb.w) * base;

    ((float4*)&g_coeff[0][0][0])[i] = s;
}

// ---------------------------------------------------------------------------
// Kernel 3: fused recombine + LayerNorm, ROWS rows (same batch) per block.
// 256 threads, each owns one float4 of h. Coefficients stay in registers.
// ---------------------------------------------------------------------------
__global__ void __launch_bounds__(256) fuse_ln_kernel(
    const float* __restrict__ x,
    const float* __restrict__ sqrt_beta,
    const float* __restrict__ gamma,
    const float* __restrict__ beta,
    float* __restrict__ out)
{
    const int base = blockIdx.x * ROWS;      // first row (b*NS + s)
    const int b    = base >> 11;             // / 2048 (ROWS divides 2048)
    const int tid  = threadIdx.x;
    const int lane = tid & 31, w = tid >> 5;

    // per-(b,h) constants, held in registers for all ROWS rows
    const float4 C0 = ((const float4*)g_coeff[b][0])[tid];
    const float4 C1 = ((const float4*)g_coeff[b][1])[tid];
    const float4 S1 = ((const float4*)g_coeff[b][2])[tid];
    const float4 C2 = ((const float4*)g_coeff[b][3])[tid];
    const float4 S2 = ((const float4*)g_coeff[b][4])[tid];
    const float4 C3 = ((const float4*)g_coeff[b][5])[tid];
    const float4 S3 = ((const float4*)g_coeff[b][6])[tid];
    const float4 sb = ((const float4*)sqrt_beta)[tid];
    const float4 gv = ((const float4*)gamma)[tid];
    const float4 bv = ((const float4*)beta)[tid];
    float4 p;   // 1 + beta^2
    p.x = 1.0f + sb.x * sb.x; p.y = 1.0f + sb.y * sb.y;
    p.z = 1.0f + sb.z * sb.z; p.w = 1.0f + sb.w * sb.w;

    __shared__ float2 sred[2][8];

    const float4* __restrict__ xrow = (const float4*)(x + (size_t)base * NH) + tid;
    float4* __restrict__       orow = (float4*)(out + (size_t)base * NH) + tid;

    float4 xv = *xrow;   // prefetch row 0

#pragma unroll
    for (int r = 0; r < ROWS; r++) {
        const int s = (base + r) & (NS - 1);
        const float4 t0 = *(const float4*)&g_tw[s][0];
        const float4 t1 = *(const float4*)&g_tw[s][4];
        const float c1 = t0.x, s1 = t0.y, c2 = t0.z, s2 = t0.w;
        const float c3 = t1.x, s3 = t1.y;

        const float4 xc = xv;
        if (r + 1 < ROWS) xv = xrow[(size_t)(r + 1) * NH4];  // prefetch next row

        float4 val;
        val.x = C0.x + C1.x*c1 + S1.x*s1 + C2.x*c2 + S2.x*s2 + C3.x*c3 + S3.x*s3 + p.x*xc.x;
        val.y = C0.y + C1.y*c1 + S1.y*s1 + C2.y*c2 + S2.y*s2 + C3.y*c3 + S3.y*s3 + p.y*xc.y;
        val.z = C0.z + C1.z*c1 + S1.z*s1 + C2.z*c2 + S2.z*s2 + C3.z*c3 + S3.z*s3 + p.z*xc.z;
        val.w = C0.w + C1.w*c1 + S1.w*s1 + C2.w*c2 + S2.w*s2 + C3.w*c3 + S3.w*s3 + p.w*xc.w;

        float lsum = val.x + val.y + val.z + val.w;
        float lsq  = val.x*val.x + val.y*val.y + val.z*val.z + val.w*val.w;

#pragma unroll
        for (int o = 16; o > 0; o >>= 1) {
            lsum += __shfl_down_sync(0xffffffffu, lsum, o);
            lsq  += __shfl_down_sync(0xffffffffu, lsq,  o);
        }
        if (lane == 0) sred[r & 1][w] = make_float2(lsum, lsq);
        __syncthreads();

        // every warp redundantly reduces the 8 warp partials (no 2nd barrier)
        float a  = (lane < 8) ? sred[r & 1][lane].x : 0.f;
        float q  = (lane < 8) ? sred[r & 1][lane].y : 0.f;
#pragma unroll
        for (int o = 4; o > 0; o >>= 1) {
            a += __shfl_down_sync(0xffffffffu, a, o);
            q += __shfl_down_sync(0xffffffffu, q, o);
        }
        a = __shfl_sync(0xffffffffu, a, 0);
        q = __shfl_sync(0xffffffffu, q, 0);

        const float mean = a * (1.0f / (float)NH);
        const float var  = q * (1.0f / (float)NH) - mean * mean;
        const float rstd = rsqrtf(var + LN_EPS);

        float4 o4;
        o4.x = (val.x - mean) * rstd * gv.x + bv.x;
        o4.y = (val.y - mean) * rstd * gv.y + bv.y;
        o4.z = (val.z - mean) * rstd * gv.z + bv.z;
        o4.w = (val.w - mean) * rstd * gv.w + bv.w;
        orow[(size_t)r * NH4] = o4;
    }
}

// ---------------------------------------------------------------------------
// launch
// ---------------------------------------------------------------------------
extern "C" void kernel_launch(void* const* d_in, const int* in_sizes, int n_in,
                              void* d_out, int out_size) {
    const float* x         = (const float*)d_in[0];
    const float* sqrt_beta = (const float*)d_in[1];
    const float* ln_gamma  = (const float*)d_in[2];
    const float* ln_beta   = (const float*)d_in[3];
    float* out = (float*)d_out;

    twiddle_kernel<<<(NS + 255) / 256, 256>>>();

    dim3 g1(NB, NCHUNK);
    coeff_partial_kernel<<<g1, 256>>>(x);

    const int n4 = NB * NCOEF * NH4;
    coeff_reduce_kernel<<<(n4 + 255) / 256, 256>>>(sqrt_beta);

    fuse_ln_kernel<<<NB * NS / ROWS, 256>>>(x, sqrt_beta, ln_gamma, ln_beta, out);
}

// round 3
// speedup vs baseline: 1.2931x; 1.2249x over previous
#include <cuda_runtime.h>
#include <math.h>

#define NB 16
#define NS 2048
#define NH 1024
#define NH4 (NH / 4)
#define NCOEF 7          // C0, C1, S1, C2, S2, C3, S3
#define NCHUNK 32
#define SCHUNK (NS / NCHUNK)   // 64
#define ROWS 16                // rows per block in fuse_ln
#define BATCH 4                // rows per barrier
#define LN_EPS 1e-12f

// twiddles: per s, {cos1,sin1,cos2,sin2,cos3,sin3,0,0} (float4-aligned pairs)
__device__ __align__(16) float g_tw[NS][8];
// deterministic partial reductions, then final (pre-scaled) coefficients
__device__ float g_partial[NCHUNK][NB][NCOEF][NH];
__device__ float g_coeff[NB][NCOEF][NH];

__device__ __forceinline__ float4 f4zero() { return make_float4(0.f, 0.f, 0.f, 0.f); }

// ---------------------------------------------------------------------------
// Kernel 0: twiddle table via sincospif (exact rational arg, MUFU-fast)
// ---------------------------------------------------------------------------
__global__ void twiddle_kernel() {
    int s = blockIdx.x * blockDim.x + threadIdx.x;
    if (s >= NS) return;
#pragma unroll
    for (int k = 1; k <= 3; k++) {
        // angle = 2*pi*k*s/NS = pi * (2*k*s/NS); 2ks/2048 = ks/1024 exact in fp32
        float frac = (float)(k * s) * (1.0f / 1024.0f);
        float sv, cv;
        sincospif(frac, &sv, &cv);
        g_tw[s][2 * (k - 1)]     = cv;
        g_tw[s][2 * (k - 1) + 1] = sv;
    }
    g_tw[s][6] = 0.f;
    g_tw[s][7] = 0.f;
}

// ---------------------------------------------------------------------------
// Kernel 1: partial DFT coefficient sums, float4-vectorized.
// grid = (NB, NCHUNK), block = 256 (one thread per 4 h-values)
// ---------------------------------------------------------------------------
__global__ void __launch_bounds__(256) coeff_partial_kernel(const float* __restrict__ x) {
    const int b     = blockIdx.x;
    const int chunk = blockIdx.y;
    const int s0    = chunk * SCHUNK;
    const int tid   = threadIdx.x;

    __shared__ float4 tw4[SCHUNK][2];
    for (int i = tid; i < SCHUNK * 2; i += 256)
        ((float4*)tw4)[i] = ((const float4*)g_tw)[s0 * 2 + i];
    __syncthreads();

    float4 a0 = f4zero(), a1 = f4zero(), b1 = f4zero(),
           a2 = f4zero(), b2 = f4zero(), a3 = f4zero(), b3 = f4zero();

    const float4* __restrict__ xp =
        (const float4*)(x + ((size_t)b * NS + s0) * NH) + tid;

#pragma unroll 8
    for (int j = 0; j < SCHUNK; j++) {
        float4 v = __ldcs(&xp[(size_t)j * NH4]);
        float4 t0 = tw4[j][0];
        float4 t1 = tw4[j][1];
        float c1 = t0.x, s1 = t0.y, c2 = t0.z, s2 = t0.w;
        float c3 = t1.x, s3 = t1.y;
        a0.x += v.x; a0.y += v.y; a0.z += v.z; a0.w += v.w;
        a1.x = fmaf(v.x, c1, a1.x); a1.y = fmaf(v.y, c1, a1.y);
        a1.z = fmaf(v.z, c1, a1.z); a1.w = fmaf(v.w, c1, a1.w);
        b1.x = fmaf(v.x, s1, b1.x); b1.y = fmaf(v.y, s1, b1.y);
        b1.z = fmaf(v.z, s1, b1.z); b1.w = fmaf(v.w, s1, b1.w);
        a2.x = fmaf(v.x, c2, a2.x); a2.y = fmaf(v.y, c2, a2.y);
        a2.z = fmaf(v.z, c2, a2.z); a2.w = fmaf(v.w, c2, a2.w);
        b2.x = fmaf(v.x, s2, b2.x); b2.y = fmaf(v.y, s2, b2.y);
        b2.z = fmaf(v.z, s2, b2.z); b2.w = fmaf(v.w, s2, b2.w);
        a3.x = fmaf(v.x, c3, a3.x); a3.y = fmaf(v.y, c3, a3.y);
        a3.z = fmaf(v.z, c3, a3.z); a3.w = fmaf(v.w, c3, a3.w);
        b3.x = fmaf(v.x, s3, b3.x); b3.y = fmaf(v.y, s3, b3.y);
        b3.z = fmaf(v.z, s3, b3.z); b3.w = fmaf(v.w, s3, b3.w);
    }

    ((float4*)g_partial[chunk][b][0])[tid] = a0;
    ((float4*)g_partial[chunk][b][1])[tid] = a1;
    ((float4*)g_partial[chunk][b][2])[tid] = b1;
    ((float4*)g_partial[chunk][b][3])[tid] = a2;
    ((float4*)g_partial[chunk][b][4])[tid] = b2;
    ((float4*)g_partial[chunk][b][5])[tid] = a3;
    ((float4*)g_partial[chunk][b][6])[tid] = b3;
}

// ---------------------------------------------------------------------------
// Kernel 2: reduce NCHUNK partials (deterministic) and pre-scale:
//   C0 = A0 * (1-beta^2)/S ;  Ck = 2*Ak*(1-beta^2)/S ;  Sk = 2*Bk*(1-beta^2)/S
// so fuse_ln computes val = C0 + sum(Ck*ck + Sk*sk) + (1+beta^2)*x
// ---------------------------------------------------------------------------
__global__ void coeff_reduce_kernel(const float* __restrict__ sqrt_beta) {
    const int i = blockIdx.x * blockDim.x + threadIdx.x;   // float4 index
    const int N4 = NB * NCOEF * NH4;
    if (i >= N4) return;

    const int h4 = i % NH4;
    const int k  = (i / NH4) % NCOEF;

    const float4* p = (const float4*)&g_partial[0][0][0][0];
    float4 s = f4zero();
#pragma unroll
    for (int c = 0; c < NCHUNK; c++) {
        float4 v = p[(size_t)c * N4 + i];
        s.x += v.x; s.y += v.y; s.z += v.z; s.w += v.w;
    }

    const float4 sb = ((const float4*)sqrt_beta)[h4];
    const float base = (k == 0 ? 1.0f : 2.0f) / (float)NS;
    s.x *= (1.0f - sb.x * sb.x) * base;
    s.y *= (1.0f - sb.y * sb.y) * base;
    s.z *= (1.0f - sb.z * sb.z) * base;
    s.w *= (1.0f - sb.w * sb.w) * base;

    ((float4*)&g_coeff[0][0][0])[i] = s;
}

// ---------------------------------------------------------------------------
// Kernel 3: fused recombine + LayerNorm.
// ROWS rows (same batch b) per block, BATCH=4 rows per __syncthreads.
// 256 threads; each thread owns one float4 of h; coefficients in registers.
// Cross-warp reduce of all 4 rows in ONE butterfly (lane = row*8 + warp).
// ---------------------------------------------------------------------------
__global__ void __launch_bounds__(256, 3) fuse_ln_kernel(
    const float* __restrict__ x,
    const float* __restrict__ sqrt_beta,
    const float* __restrict__ gamma,
    const float* __restrict__ beta,
    float* __restrict__ out)
{
    const int base = blockIdx.x * ROWS;      // first row (b*NS + s)
    const int b    = base >> 11;             // / 2048 (ROWS divides 2048)
    const int tid  = threadIdx.x;
    const int lane = tid & 31, w = tid >> 5;

    // per-(b,h) constants, held in registers for all ROWS rows
    const float4 C0 = ((const float4*)g_coeff[b][0])[tid];
    const float4 C1 = ((const float4*)g_coeff[b][1])[tid];
    const float4 S1 = ((const float4*)g_coeff[b][2])[tid];
    const float4 C2 = ((const float4*)g_coeff[b][3])[tid];
    const float4 S2 = ((const float4*)g_coeff[b][4])[tid];
    const float4 C3 = ((const float4*)g_coeff[b][5])[tid];
    const float4 S3 = ((const float4*)g_coeff[b][6])[tid];
    const float4 sb = ((const float4*)sqrt_beta)[tid];
    const float4 gv = ((const float4*)gamma)[tid];
    const float4 bv = ((const float4*)beta)[tid];
    float4 p;   // 1 + beta^2
    p.x = 1.0f + sb.x * sb.x; p.y = 1.0f + sb.y * sb.y;
    p.z = 1.0f + sb.z * sb.z; p.w = 1.0f + sb.w * sb.w;

    __shared__ float2 sred[2][BATCH][8];

    const float4* __restrict__ xrow = (const float4*)(x + (size_t)base * NH) + tid;
    float4* __restrict__       orow = (float4*)(out + (size_t)base * NH) + tid;

#pragma unroll
    for (int r0 = 0; r0 < ROWS; r0 += BATCH) {
        const int buf = (r0 >> 2) & 1;
        float4 val[BATCH];

        // issue all BATCH loads (independent -> MLP 4)
#pragma unroll
        for (int i = 0; i < BATCH; i++)
            val[i] = __ldcs(&xrow[(size_t)(r0 + i) * NH4]);

        // recombine: val = C0 + sum Ck*ck + Sk*sk + p*x
#pragma unroll
        for (int i = 0; i < BATCH; i++) {
            const int s = (base + r0 + i) & (NS - 1);
            const float4 t0 = *(const float4*)&g_tw[s][0];
            const float4 t1 = *(const float4*)&g_tw[s][4];
            const float c1 = t0.x, s1 = t0.y, c2 = t0.z, s2 = t0.w;
            const float c3 = t1.x, s3 = t1.y;
            const float4 xc = val[i];
            val[i].x = fmaf(p.x, xc.x, C0.x + C1.x*c1 + S1.x*s1 + C2.x*c2 + S2.x*s2 + C3.x*c3 + S3.x*s3);
            val[i].y = fmaf(p.y, xc.y, C0.y + C1.y*c1 + S1.y*s1 + C2.y*c2 + S2.y*s2 + C3.y*c3 + S3.y*s3);
            val[i].z = fmaf(p.z, xc.z, C0.z + C1.z*c1 + S1.z*s1 + C2.z*c2 + S2.z*s2 + C3.z*c3 + S3.z*s3);
            val[i].w = fmaf(p.w, xc.w, C0.w + C1.w*c1 + S1.w*s1 + C2.w*c2 + S2.w*s2 + C3.w*c3 + S3.w*s3);
        }

        // intra-warp reduce per row
#pragma unroll
        for (int i = 0; i < BATCH; i++) {
            float lsum = val[i].x + val[i].y + val[i].z + val[i].w;
            float lsq  = val[i].x*val[i].x + val[i].y*val[i].y
                       + val[i].z*val[i].z + val[i].w*val[i].w;
#pragma unroll
            for (int o = 16; o > 0; o >>= 1) {
                lsum += __shfl_down_sync(0xffffffffu, lsum, o);
                lsq  += __shfl_down_sync(0xffffffffu, lsq,  o);
            }
            if (lane == 0) sred[buf][i][w] = make_float2(lsum, lsq);
        }
        __syncthreads();   // one barrier per BATCH rows

        // cross-warp butterfly for all 4 rows at once: lane = row*8 + srcwarp
        {
            const int rr = lane >> 3, ws = lane & 7;
            float a = sred[buf][rr][ws].x;
            float q = sred[buf][rr][ws].y;
#pragma unroll
            for (int o = 4; o > 0; o >>= 1) {
                a += __shfl_down_sync(0xffffffffu, a, o);
                q += __shfl_down_sync(0xffffffffu, q, o);
            }
            // lane 8*i now holds row i totals; broadcast + normalize + store
#pragma unroll
            for (int i = 0; i < BATCH; i++) {
                const float aa = __shfl_sync(0xffffffffu, a, 8 * i);
                const float qq = __shfl_sync(0xffffffffu, q, 8 * i);
                const float mean = aa * (1.0f / (float)NH);
                const float var  = qq * (1.0f / (float)NH) - mean * mean;
                const float rstd = rsqrtf(var + LN_EPS);
                float4 o4;
                o4.x = fmaf((val[i].x - mean) * rstd, gv.x, bv.x);
                o4.y = fmaf((val[i].y - mean) * rstd, gv.y, bv.y);
                o4.z = fmaf((val[i].z - mean) * rstd, gv.z, bv.z);
                o4.w = fmaf((val[i].w - mean) * rstd, gv.w, bv.w);
                __stcs(&orow[(size_t)(r0 + i) * NH4], o4);
            }
        }
    }
}

// ---------------------------------------------------------------------------
// launch
// ---------------------------------------------------------------------------
extern "C" void kernel_launch(void* const* d_in, const int* in_sizes, int n_in,
                              void* d_out, int out_size) {
    const float* x         = (const float*)d_in[0];
    const float* sqrt_beta = (const float*)d_in[1];
    const float* ln_gamma  = (const float*)d_in[2];
    const float* ln_beta   = (const float*)d_in[3];
    float* out = (float*)d_out;

    twiddle_kernel<<<(NS + 255) / 256, 256>>>();

    dim3 g1(NB, NCHUNK);
    coeff_partial_kernel<<<g1, 256>>>(x);

    const int n4 = NB * NCOEF * NH4;
    coeff_reduce_kernel<<<(n4 + 255) / 256, 256>>>(sqrt_beta);

    fuse_ln_kernel<<<NB * NS / ROWS, 256>>>(x, sqrt_beta, ln_gamma, ln_beta, out);
}